// round 3
// baseline (speedup 1.0000x reference)
#include <cuda_runtime.h>
#include <cuda_bf16.h>
#include <cstdint>

// Problem constants
#define BATCH 8
#define SEQ   1024
#define NH    8
#define HD    32
#define DMODEL 256
#define MTOT  (BATCH*SEQ)      // 8192
#define CTOT  (NH*HD)          // 256
#define TBL   3969             // (2*32-1)^2

// Scratch (device globals; allocation-free)
__device__ float g_Q[BATCH*NH*SEQ*HD];   // [B,H,S,HD]
__device__ float g_K[BATCH*NH*SEQ*HD];
__device__ float g_V[BATCH*NH*SEQ*HD];
__device__ float g_X[MTOT*CTOT];         // [B,S,H*HD] attn output

// ---------------------------------------------------------------------------
// Generic SGEMM: out = (A[M=8192,K=256] @ W[K=256,N=256] + bias[N]) * scale
// permute=1: write as [B,H,S,HD]; permute=0: plain row-major [M,N]
// Tiles: BM=128, BN=128, BK=16, 256 threads, 8x8 per thread.
// ---------------------------------------------------------------------------
__global__ __launch_bounds__(256) void gemm_kernel(
    const float* __restrict__ A, const float* __restrict__ W,
    const float* __restrict__ bias, float* __restrict__ out,
    float scale, int permute)
{
    const int m0 = blockIdx.x * 128;
    const int n0 = blockIdx.y * 128;
    __shared__ float As[16][128];
    __shared__ float Bs[16][128];

    const int tid = threadIdx.x;
    const int tx = tid & 15;        // 0..15 -> 8 cols each
    const int ty = tid >> 4;        // 0..15 -> 8 rows each

    float acc[8][8];
    #pragma unroll
    for (int i = 0; i < 8; i++)
        #pragma unroll
        for (int j = 0; j < 8; j++) acc[i][j] = 0.f;

    for (int k0 = 0; k0 < 256; k0 += 16) {
        // Load A tile 128x16 (512 float4), store transposed
        #pragma unroll
        for (int i = 0; i < 2; i++) {
            int f   = tid + i * 256;         // 0..511
            int row = f >> 2;
            int c4  = f & 3;
            float4 v = *(const float4*)(A + (size_t)(m0 + row) * 256 + k0 + c4 * 4);
            As[c4*4+0][row] = v.x;
            As[c4*4+1][row] = v.y;
            As[c4*4+2][row] = v.z;
            As[c4*4+3][row] = v.w;
        }
        // Load B tile 16x128 (512 float4)
        #pragma unroll
        for (int i = 0; i < 2; i++) {
            int f   = tid + i * 256;
            int row = f >> 5;
            int c4  = f & 31;
            *(float4*)(&Bs[row][c4*4]) =
                *(const float4*)(W + (size_t)(k0 + row) * 256 + n0 + c4 * 4);
        }
        __syncthreads();

        #pragma unroll
        for (int k = 0; k < 16; k++) {
            float a[8], b[8];
            const float4* ap = (const float4*)&As[k][ty * 8];
            const float4* bp = (const float4*)&Bs[k][tx * 8];
            float4 a0 = ap[0], a1 = ap[1];
            float4 b0 = bp[0], b1 = bp[1];
            a[0]=a0.x; a[1]=a0.y; a[2]=a0.z; a[3]=a0.w;
            a[4]=a1.x; a[5]=a1.y; a[6]=a1.z; a[7]=a1.w;
            b[0]=b0.x; b[1]=b0.y; b[2]=b0.z; b[3]=b0.w;
            b[4]=b1.x; b[5]=b1.y; b[6]=b1.z; b[7]=b1.w;
            #pragma unroll
            for (int i = 0; i < 8; i++)
                #pragma unroll
                for (int j = 0; j < 8; j++)
                    acc[i][j] += a[i] * b[j];
        }
        __syncthreads();
    }

    // Epilogue
    #pragma unroll
    for (int i = 0; i < 8; i++) {
        int r = m0 + ty * 8 + i;
        #pragma unroll
        for (int j4 = 0; j4 < 8; j4 += 4) {
            int c = n0 + tx * 8 + j4;
            float4 v;
            v.x = (acc[i][j4+0] + bias[c+0]) * scale;
            v.y = (acc[i][j4+1] + bias[c+1]) * scale;
            v.z = (acc[i][j4+2] + bias[c+2]) * scale;
            v.w = (acc[i][j4+3] + bias[c+3]) * scale;
            if (permute) {
                int bb = r >> 10, ss = r & 1023;
                int h  = c >> 5,  hd = c & 31;
                *(float4*)(out + ((size_t)(bb * NH + h) * SEQ + ss) * HD + hd) = v;
            } else {
                *(float4*)(out + (size_t)r * 256 + c) = v;
            }
        }
    }
}

// ---------------------------------------------------------------------------
// Flash-style attention with analytic Swin relative bias.
// Grid: (4, 64) = (query chunks of 256, b*h). One thread per query.
// Q/K/V layout: [B,H,S,HD]. Output X: [B,S,H*HD] row-major.
// ---------------------------------------------------------------------------
__global__ __launch_bounds__(256) void attn_kernel(
    const float* __restrict__ Q, const float* __restrict__ K,
    const float* __restrict__ V, const float* __restrict__ rel,
    float* __restrict__ X)
{
    __shared__ float  tb[TBL];        // rel_table column for this head
    __shared__ float4 Ks[128 * 8];    // 128 keys x 32 floats
    __shared__ float4 Vs[128 * 8];

    const int bh = blockIdx.y;
    const int h  = bh & 7;
    const int b  = bh >> 3;
    const int tid = threadIdx.x;
    const int s  = blockIdx.x * 256 + tid;     // query index within (b,h)

    for (int i = tid; i < TBL; i += 256) tb[i] = rel[i * NH + h];

    const int yq = s >> 5, xq = s & 31;

    float4 fq[8];
    {
        const float4* qp = (const float4*)(Q + ((size_t)bh * SEQ + s) * HD);
        #pragma unroll
        for (int u = 0; u < 8; u++) fq[u] = qp[u];
    }

    float m = -1e30f, l = 0.f;
    float4 a4[8];
    #pragma unroll
    for (int u = 0; u < 8; u++) a4[u] = make_float4(0.f, 0.f, 0.f, 0.f);

    const float4* Kg = (const float4*)(K + (size_t)bh * SEQ * HD);
    const float4* Vg = (const float4*)(V + (size_t)bh * SEQ * HD);

    for (int kt = 0; kt < 8; kt++) {           // 8 tiles of 128 keys
        __syncthreads();
        #pragma unroll
        for (int i = 0; i < 4; i++) {
            int f = tid + i * 256;             // 0..1023
            Ks[f] = Kg[kt * 1024 + f];
            Vs[f] = Vg[kt * 1024 + f];
        }
        __syncthreads();

        #pragma unroll 1
        for (int jc = 0; jc < 8; jc++) {       // chunks of 16 keys
            float sc[16];
            const int kbase = kt * 128 + jc * 16;
            #pragma unroll
            for (int j = 0; j < 16; j++) {
                const float4* kp = &Ks[(jc * 16 + j) * 8];
                float p0 = 0.f, p1 = 0.f;
                #pragma unroll
                for (int u = 0; u < 8; u += 2) {
                    float4 kv0 = kp[u];
                    float4 kv1 = kp[u + 1];
                    p0 += fq[u].x   * kv0.x; p0 += fq[u].y   * kv0.y;
                    p0 += fq[u].z   * kv0.z; p0 += fq[u].w   * kv0.w;
                    p1 += fq[u+1].x * kv1.x; p1 += fq[u+1].y * kv1.y;
                    p1 += fq[u+1].z * kv1.z; p1 += fq[u+1].w * kv1.w;
                }
                const int kk = kbase + j;
                const int idx = (yq - (kk >> 5) + 31) * 63 + (xq - (kk & 31) + 31);
                sc[j] = p0 + p1 + tb[idx];
            }
            // chunk max + online-softmax rescale
            float mx = sc[0];
            #pragma unroll
            for (int j = 1; j < 16; j++) mx = fmaxf(mx, sc[j]);
            float nm = fmaxf(m, mx);
            float corr = __expf(m - nm);
            m = nm;
            l *= corr;
            #pragma unroll
            for (int u = 0; u < 8; u++) {
                a4[u].x *= corr; a4[u].y *= corr;
                a4[u].z *= corr; a4[u].w *= corr;
            }
            #pragma unroll
            for (int j = 0; j < 16; j++) {
                float p = __expf(sc[j] - m);
                l += p;
                const float4* vp = &Vs[(jc * 16 + j) * 8];
                #pragma unroll
                for (int u = 0; u < 8; u++) {
                    float4 vv = vp[u];
                    a4[u].x += p * vv.x; a4[u].y += p * vv.y;
                    a4[u].z += p * vv.z; a4[u].w += p * vv.w;
                }
            }
        }
    }

    const float inv = 1.f / l;
    float4* xo = (float4*)(X + ((size_t)(b * SEQ + s)) * CTOT + h * HD);
    #pragma unroll
    for (int u = 0; u < 8; u++) {
        float4 v;
        v.x = a4[u].x * inv; v.y = a4[u].y * inv;
        v.z = a4[u].z * inv; v.w = a4[u].w * inv;
        xo[u] = v;
    }
}

// ---------------------------------------------------------------------------
extern "C" void kernel_launch(void* const* d_in, const int* in_sizes, int n_in,
                              void* d_out, int out_size)
{
    const float* xq  = (const float*)d_in[0];
    const float* xkv = (const float*)d_in[1];
    const float* Wq  = (const float*)d_in[2];
    const float* bq  = (const float*)d_in[3];
    const float* Wk  = (const float*)d_in[4];
    const float* bk  = (const float*)d_in[5];
    const float* Wv  = (const float*)d_in[6];
    const float* bv  = (const float*)d_in[7];
    const float* rel = (const float*)d_in[8];
    const float* Wo  = (const float*)d_in[9];
    const float* bo  = (const float*)d_in[10];

    void *pq, *pk, *pv, *px;
    cudaGetSymbolAddress(&pq, g_Q);
    cudaGetSymbolAddress(&pk, g_K);
    cudaGetSymbolAddress(&pv, g_V);
    cudaGetSymbolAddress(&px, g_X);

    const float qscale = 0.17677669529663687f;  // 1/sqrt(32)

    dim3 gg(MTOT / 128, CTOT / 128);            // (64, 2)
    gemm_kernel<<<gg, 256>>>(xq,  Wq, bq, (float*)pq, qscale, 1);
    gemm_kernel<<<gg, 256>>>(xkv, Wk, bk, (float*)pk, 1.f,    1);
    gemm_kernel<<<gg, 256>>>(xkv, Wv, bv, (float*)pv, 1.f,    1);

    attn_kernel<<<dim3(4, 64), 256>>>((const float*)pq, (const float*)pk,
                                      (const float*)pv, rel, (float*)px);

    gemm_kernel<<<gg, 256>>>((const float*)px, Wo, bo, (float*)d_out, 1.f, 0);
}

// round 5
// speedup vs baseline: 1.0384x; 1.0384x over previous
#include <cuda_runtime.h>
#include <cuda_bf16.h>
#include <cstdint>

// Problem constants
#define BATCH 8
#define SEQ   1024
#define NH    8
#define HD    32
#define MTOT  (BATCH*SEQ)      // 8192
#define CTOT  (NH*HD)          // 256
#define TBL   3969             // (2*32-1)^2

// Scratch (device globals; allocation-free)
__device__ float g_Q[BATCH*NH*SEQ*HD];   // [B,H,S,HD]
__device__ float g_K[BATCH*NH*SEQ*HD];
__device__ float g_V[BATCH*NH*SEQ*HD];
__device__ float g_X[MTOT*CTOT];         // [B,S,H*HD]

// ---------------------------------------------------------------------------
// Packed f32x2 helpers (Blackwell FFMA2 path; ptxas never emits these from C++)
// ---------------------------------------------------------------------------
typedef unsigned long long u64;

__device__ __forceinline__ void ffma2(u64& acc, u64 a, u64 b) {
    asm("fma.rn.f32x2 %0, %1, %2, %0;" : "+l"(acc) : "l"(a), "l"(b));
}
__device__ __forceinline__ void fmul2(u64& d, u64 a, u64 b) {
    asm("mul.rn.f32x2 %0, %1, %2;" : "=l"(d) : "l"(a), "l"(b));
}
__device__ __forceinline__ u64 pk2(float lo, float hi) {
    u64 r;
    asm("mov.b64 %0, {%1, %2};" : "=l"(r) : "f"(lo), "f"(hi));
    return r;
}
__device__ __forceinline__ float2 upk2(u64 v) {
    float2 r;
    asm("mov.b64 {%0, %1}, %2;" : "=f"(r.x), "=f"(r.y) : "l"(v));
    return r;
}

// ---------------------------------------------------------------------------
// SGEMM with FFMA2: out = (A[8192,256] @ W[256,256] + bias[N]) * scale
// Tiles: BM=128, BN=128, BK=16, 256 threads, 8x8 per thread (4 packed pairs).
// permute=1: write as [B,H,S,HD]; permute=0: plain row-major [M,N].
// ---------------------------------------------------------------------------
__global__ __launch_bounds__(256) void gemm_kernel(
    const float* __restrict__ A, const float* __restrict__ W,
    const float* __restrict__ bias, float* __restrict__ out,
    float scale, int permute)
{
    const int m0 = blockIdx.x * 128;
    const int n0 = blockIdx.y * 128;
    __shared__ float As[16][128];
    __shared__ float Bs[16][128];

    const int tid = threadIdx.x;
    const int tx = tid & 15;        // 0..15 -> 8 cols each
    const int ty = tid >> 4;        // 0..15 -> 8 rows each

    u64 acc2[8][4];                 // 8 rows x 4 col-pairs
    #pragma unroll
    for (int i = 0; i < 8; i++)
        #pragma unroll
        for (int j = 0; j < 4; j++) acc2[i][j] = 0ull;

    for (int k0 = 0; k0 < 256; k0 += 16) {
        // Load A tile 128x16 (512 float4), store transposed
        #pragma unroll
        for (int i = 0; i < 2; i++) {
            int f   = tid + i * 256;         // 0..511
            int row = f >> 2;
            int c4  = f & 3;
            float4 v = *(const float4*)(A + (size_t)(m0 + row) * 256 + k0 + c4 * 4);
            As[c4*4+0][row] = v.x;
            As[c4*4+1][row] = v.y;
            As[c4*4+2][row] = v.z;
            As[c4*4+3][row] = v.w;
        }
        // Load B tile 16x128 (512 float4)
        #pragma unroll
        for (int i = 0; i < 2; i++) {
            int f   = tid + i * 256;
            int row = f >> 5;
            int c4  = f & 31;
            *(float4*)(&Bs[row][c4*4]) =
                *(const float4*)(W + (size_t)(k0 + row) * 256 + n0 + c4 * 4);
        }
        __syncthreads();

        #pragma unroll
        for (int k = 0; k < 16; k++) {
            // a: 8 scalars -> 8 broadcast pairs; b: 4 packed pairs
            const float*      ap = &As[k][ty * 8];
            const ulonglong2* bp = (const ulonglong2*)&Bs[k][tx * 8];
            ulonglong2 bq0 = bp[0], bq1 = bp[1];
            u64 b2[4] = { bq0.x, bq0.y, bq1.x, bq1.y };
            #pragma unroll
            for (int i = 0; i < 8; i++) {
                u64 aa = pk2(ap[i], ap[i]);
                #pragma unroll
                for (int j = 0; j < 4; j++)
                    ffma2(acc2[i][j], aa, b2[j]);
            }
        }
        __syncthreads();
    }

    // Epilogue
    #pragma unroll
    for (int i = 0; i < 8; i++) {
        int r = m0 + ty * 8 + i;
        #pragma unroll
        for (int j4 = 0; j4 < 2; j4++) {
            int c = n0 + tx * 8 + j4 * 4;
            float2 p0 = upk2(acc2[i][j4 * 2 + 0]);
            float2 p1 = upk2(acc2[i][j4 * 2 + 1]);
            float4 v;
            v.x = (p0.x + bias[c+0]) * scale;
            v.y = (p0.y + bias[c+1]) * scale;
            v.z = (p1.x + bias[c+2]) * scale;
            v.w = (p1.y + bias[c+3]) * scale;
            if (permute) {
                int bb = r >> 10, ss = r & 1023;
                int h  = c >> 5,  hd = c & 31;
                *(float4*)(out + ((size_t)(bb * NH + h) * SEQ + ss) * HD + hd) = v;
            } else {
                *(float4*)(out + (size_t)r * 256 + c) = v;
            }
        }
    }
}

// ---------------------------------------------------------------------------
// Flash-style attention with analytic Swin relative bias, FFMA2 math.
// Grid (8, 64), 128 threads (one query per thread), 4 CTAs/SM -> single wave.
// Q/K/V layout: [B,H,S,HD]. Output X: [B,S,H*HD] row-major.
// ---------------------------------------------------------------------------
__global__ __launch_bounds__(128, 4) void attn_kernel(
    const float* __restrict__ Q, const float* __restrict__ K,
    const float* __restrict__ V, const float* __restrict__ rel,
    float* __restrict__ X)
{
    __shared__ float  tb[TBL];        // rel_table column for this head
    __shared__ float4 Ks[128 * 8];    // 128 keys x 32 floats
    __shared__ float4 Vs[128 * 8];

    const int bh = blockIdx.y;
    const int h  = bh & 7;
    const int b  = bh >> 3;
    const int tid = threadIdx.x;
    const int s  = blockIdx.x * 128 + tid;     // query index within (b,h)

    for (int i = tid; i < TBL; i += 128) tb[i] = rel[i * NH + h];

    const int yq = s >> 5, xq = s & 31;

    // Q vector: 16 packed pairs
    u64 fq2[16];
    {
        const ulonglong2* qp = (const ulonglong2*)(Q + ((size_t)bh * SEQ + s) * HD);
        #pragma unroll
        for (int u = 0; u < 8; u++) {
            ulonglong2 q = qp[u];
            fq2[2*u]   = q.x;
            fq2[2*u+1] = q.y;
        }
    }

    float m = -1e30f, l = 0.f;
    u64 a2[16];
    #pragma unroll
    for (int u = 0; u < 16; u++) a2[u] = 0ull;

    const float4* Kg = (const float4*)(K + (size_t)bh * SEQ * HD);
    const float4* Vg = (const float4*)(V + (size_t)bh * SEQ * HD);

    for (int kt = 0; kt < 8; kt++) {           // 8 tiles of 128 keys
        __syncthreads();
        #pragma unroll
        for (int i = 0; i < 8; i++) {
            int f = tid + i * 128;             // 0..1023
            Ks[f] = Kg[kt * 1024 + f];
            Vs[f] = Vg[kt * 1024 + f];
        }
        __syncthreads();

        #pragma unroll 1
        for (int jc = 0; jc < 8; jc++) {       // chunks of 16 keys
            float sc[16];
            const int kbase = kt * 128 + jc * 16;
            #pragma unroll
            for (int j = 0; j < 16; j++) {
                const ulonglong2* kp = (const ulonglong2*)&Ks[(jc * 16 + j) * 8];
                u64 acc = 0ull;
                #pragma unroll
                for (int u = 0; u < 8; u++) {
                    ulonglong2 kv = kp[u];
                    ffma2(acc, fq2[2*u],   kv.x);
                    ffma2(acc, fq2[2*u+1], kv.y);
                }
                float2 ac = upk2(acc);
                const int kk = kbase + j;
                const int idx = (yq - (kk >> 5) + 31) * 63 + (xq - (kk & 31) + 31);
                sc[j] = ac.x + ac.y + tb[idx];
            }
            // chunk max + online-softmax rescale
            float mx = sc[0];
            #pragma unroll
            for (int j = 1; j < 16; j++) mx = fmaxf(mx, sc[j]);
            float nm = fmaxf(m, mx);
            float corr = __expf(m - nm);
            m = nm;
            l *= corr;
            u64 cc = pk2(corr, corr);
            #pragma unroll
            for (int u = 0; u < 16; u++) fmul2(a2[u], a2[u], cc);
            #pragma unroll
            for (int j = 0; j < 16; j++) {
                float p = __expf(sc[j] - m);
                l += p;
                u64 pp = pk2(p, p);
                const ulonglong2* vp = (const ulonglong2*)&Vs[(jc * 16 + j) * 8];
                #pragma unroll
                for (int u = 0; u < 8; u++) {
                    ulonglong2 vv = vp[u];
                    ffma2(a2[2*u],   pp, vv.x);
                    ffma2(a2[2*u+1], pp, vv.y);
                }
            }
        }
    }

    const float inv = 1.f / l;
    float4* xo = (float4*)(X + ((size_t)(b * SEQ + s)) * CTOT + h * HD);
    #pragma unroll
    for (int u = 0; u < 8; u++) {
        float2 p0 = upk2(a2[2*u]);
        float2 p1 = upk2(a2[2*u+1]);
        float4 v;
        v.x = p0.x * inv; v.y = p0.y * inv;
        v.z = p1.x * inv; v.w = p1.y * inv;
        xo[u] = v;
    }
}

// ---------------------------------------------------------------------------
extern "C" void kernel_launch(void* const* d_in, const int* in_sizes, int n_in,
                              void* d_out, int out_size)
{
    const float* xq  = (const float*)d_in[0];
    const float* xkv = (const float*)d_in[1];
    const float* Wq  = (const float*)d_in[2];
    const float* bq  = (const float*)d_in[3];
    const float* Wk  = (const float*)d_in[4];
    const float* bk  = (const float*)d_in[5];
    const float* Wv  = (const float*)d_in[6];
    const float* bv  = (const float*)d_in[7];
    const float* rel = (const float*)d_in[8];
    const float* Wo  = (const float*)d_in[9];
    const float* bo  = (const float*)d_in[10];

    void *pq, *pk, *pv, *px;
    cudaGetSymbolAddress(&pq, g_Q);
    cudaGetSymbolAddress(&pk, g_K);
    cudaGetSymbolAddress(&pv, g_V);
    cudaGetSymbolAddress(&px, g_X);

    // Hint max shared carveout so 4 attn CTAs/SM fit (190KB/SM).
    // Idempotent, no enqueue/alloc — safe under graph capture.
    cudaFuncSetAttribute(attn_kernel,
                         cudaFuncAttributePreferredSharedMemoryCarveout, 100);

    const float qscale = 0.17677669529663687f;  // 1/sqrt(32)

    dim3 gg(MTOT / 128, CTOT / 128);            // (64, 2)
    gemm_kernel<<<gg, 256>>>(xq,  Wq, bq, (float*)pq, qscale, 1);
    gemm_kernel<<<gg, 256>>>(xkv, Wk, bk, (float*)pk, 1.f,    1);
    gemm_kernel<<<gg, 256>>>(xkv, Wv, bv, (float*)pv, 1.f,    1);

    attn_kernel<<<dim3(8, 64), 128>>>((const float*)pq, (const float*)pk,
                                      (const float*)pv, rel, (float*)px);

    gemm_kernel<<<gg, 256>>>((const float*)px, Wo, bo, (float*)d_out, 1.f, 0);
}

// round 6
// speedup vs baseline: 1.2101x; 1.1654x over previous
#include <cuda_runtime.h>
#include <cuda_bf16.h>
#include <cstdint>

// Problem constants
#define BATCH 8
#define SEQ   1024
#define NH    8
#define HD    32
#define MTOT  (BATCH*SEQ)      // 8192
#define CTOT  (NH*HD)          // 256
#define TBL   3969             // (2*32-1)^2

// Scratch (device globals; allocation-free)
__device__ float g_Q[BATCH*NH*SEQ*HD];   // [B,H,S,HD]
__device__ float g_K[BATCH*NH*SEQ*HD];
__device__ float g_V[BATCH*NH*SEQ*HD];
__device__ float g_X[MTOT*CTOT];         // [B,S,H*HD]

// ---------------------------------------------------------------------------
// Packed f32x2 helpers (Blackwell FFMA2; ptxas never emits these from C++)
// ---------------------------------------------------------------------------
typedef unsigned long long u64;

__device__ __forceinline__ void ffma2(u64& acc, u64 a, u64 b) {
    asm("fma.rn.f32x2 %0, %1, %2, %0;" : "+l"(acc) : "l"(a), "l"(b));
}
__device__ __forceinline__ void fmul2(u64& d, u64 a, u64 b) {
    asm("mul.rn.f32x2 %0, %1, %2;" : "=l"(d) : "l"(a), "l"(b));
}
__device__ __forceinline__ u64 pk2(float lo, float hi) {
    u64 r;
    asm("mov.b64 %0, {%1, %2};" : "=l"(r) : "f"(lo), "f"(hi));
    return r;
}
__device__ __forceinline__ float2 upk2(u64 v) {
    float2 r;
    asm("mov.b64 {%0, %1}, %2;" : "=f"(r.x), "=f"(r.y) : "l"(v));
    return r;
}

// ---------------------------------------------------------------------------
// SGEMM with FFMA2: out = (A[8192,256] @ W[256,256] + bias[N]) * scale
// BM=64, BN=128, BK=16, 128 threads, 8x8 per thread. Grid (128,2) = 256 CTAs.
// A tile stored PRE-DUPLICATED as u64 (both lanes = same value) -> inner loop
// is 8 broadcast LDS.64 + 2 LDS.128 per k, zero pack MOVs.
// permute=1: write as [B,H,S,HD]; permute=0: row-major [M,N].
// ---------------------------------------------------------------------------
__global__ __launch_bounds__(128) void gemm_kernel(
    const float* __restrict__ A, const float* __restrict__ W,
    const float* __restrict__ bias, float* __restrict__ out,
    float scale, int permute)
{
    const int m0 = blockIdx.x * 64;
    const int n0 = blockIdx.y * 128;
    __shared__ u64   As2[16][64];    // [k][row], lanes duplicated (8KB)
    __shared__ float Bs[16][128];    // (8KB)

    const int tid = threadIdx.x;
    const int tx = tid & 15;         // 0..15 -> 8 cols each
    const int ty = tid >> 4;         // 0..7  -> 8 rows each

    u64 acc2[8][4];
    #pragma unroll
    for (int i = 0; i < 8; i++)
        #pragma unroll
        for (int j = 0; j < 4; j++) acc2[i][j] = 0ull;

    for (int k0 = 0; k0 < 256; k0 += 16) {
        // A tile 64x16 (256 float4), write dup-u64 transposed
        #pragma unroll
        for (int i = 0; i < 2; i++) {
            int f   = tid + i * 128;          // 0..255
            int row = f >> 2;
            int c4  = f & 3;
            float4 v = *(const float4*)(A + (size_t)(m0 + row) * 256 + k0 + c4 * 4);
            As2[c4*4+0][row] = pk2(v.x, v.x);
            As2[c4*4+1][row] = pk2(v.y, v.y);
            As2[c4*4+2][row] = pk2(v.z, v.z);
            As2[c4*4+3][row] = pk2(v.w, v.w);
        }
        // B tile 16x128 (512 float4)
        #pragma unroll
        for (int i = 0; i < 4; i++) {
            int f   = tid + i * 128;
            int row = f >> 5;
            int c4  = f & 31;
            *(float4*)(&Bs[row][c4*4]) =
                *(const float4*)(W + (size_t)(k0 + row) * 256 + n0 + c4 * 4);
        }
        __syncthreads();

        #pragma unroll
        for (int k = 0; k < 16; k++) {
            const u64*        ap = &As2[k][ty * 8];
            const ulonglong2* bp = (const ulonglong2*)&Bs[k][tx * 8];
            ulonglong2 bq0 = bp[0], bq1 = bp[1];
            u64 b2[4] = { bq0.x, bq0.y, bq1.x, bq1.y };
            u64 a2[8];
            #pragma unroll
            for (int i = 0; i < 8; i++) a2[i] = ap[i];
            #pragma unroll
            for (int i = 0; i < 8; i++)
                #pragma unroll
                for (int j = 0; j < 4; j++)
                    ffma2(acc2[i][j], a2[i], b2[j]);
        }
        __syncthreads();
    }

    // Epilogue
    #pragma unroll
    for (int i = 0; i < 8; i++) {
        int r = m0 + ty * 8 + i;
        #pragma unroll
        for (int j4 = 0; j4 < 2; j4++) {
            int c = n0 + tx * 8 + j4 * 4;
            float2 p0 = upk2(acc2[i][j4 * 2 + 0]);
            float2 p1 = upk2(acc2[i][j4 * 2 + 1]);
            float4 v;
            v.x = (p0.x + bias[c+0]) * scale;
            v.y = (p0.y + bias[c+1]) * scale;
            v.z = (p1.x + bias[c+2]) * scale;
            v.w = (p1.y + bias[c+3]) * scale;
            if (permute) {
                int bb = r >> 10, ss = r & 1023;
                int h  = c >> 5,  hd = c & 31;
                *(float4*)(out + ((size_t)(bb * NH + h) * SEQ + ss) * HD + hd) = v;
            } else {
                *(float4*)(out + (size_t)r * 256 + c) = v;
            }
        }
    }
}

// ---------------------------------------------------------------------------
// Flash-style attention, analytic Swin bias, FFMA2, TWO queries per thread
// (s and s+128) so each broadcast K/V LDS feeds 4 FFMA2 instead of 2.
// Grid (4, 64), 128 threads, ~255 regs, 2 CTAs/SM -> 256 CTAs single wave.
// ---------------------------------------------------------------------------
__global__ __launch_bounds__(128, 2) void attn_kernel(
    const float* __restrict__ Q, const float* __restrict__ K,
    const float* __restrict__ V, const float* __restrict__ rel,
    float* __restrict__ X)
{
    __shared__ float  tb[TBL];        // rel_table column for this head
    __shared__ float4 Ks[128 * 8];    // 128 keys x 32 floats
    __shared__ float4 Vs[128 * 8];

    const int bh = blockIdx.y;
    const int h  = bh & 7;
    const int b  = bh >> 3;
    const int tid = threadIdx.x;
    const int s0 = blockIdx.x * 256 + tid;     // query 0
    const int s1 = s0 + 128;                   // query 1

    for (int i = tid; i < TBL; i += 128) tb[i] = rel[i * NH + h];

    const int yq0 = s0 >> 5, xq0 = s0 & 31;
    const int yq1 = s1 >> 5, xq1 = s1 & 31;

    // Q vectors: 16 packed pairs each
    u64 q0[16], q1[16];
    {
        const ulonglong2* qp0 = (const ulonglong2*)(Q + ((size_t)bh * SEQ + s0) * HD);
        const ulonglong2* qp1 = (const ulonglong2*)(Q + ((size_t)bh * SEQ + s1) * HD);
        #pragma unroll
        for (int u = 0; u < 8; u++) {
            ulonglong2 a = qp0[u]; q0[2*u] = a.x; q0[2*u+1] = a.y;
            ulonglong2 c = qp1[u]; q1[2*u] = c.x; q1[2*u+1] = c.y;
        }
    }

    float m0 = -1e30f, l0 = 0.f, m1 = -1e30f, l1 = 0.f;
    u64 a0[16], a1[16];
    #pragma unroll
    for (int u = 0; u < 16; u++) { a0[u] = 0ull; a1[u] = 0ull; }

    const float4* Kg = (const float4*)(K + (size_t)bh * SEQ * HD);
    const float4* Vg = (const float4*)(V + (size_t)bh * SEQ * HD);

    for (int kt = 0; kt < 8; kt++) {           // 8 tiles of 128 keys
        __syncthreads();
        #pragma unroll
        for (int i = 0; i < 8; i++) {
            int f = tid + i * 128;             // 0..1023
            Ks[f] = Kg[kt * 1024 + f];
            Vs[f] = Vg[kt * 1024 + f];
        }
        __syncthreads();

        #pragma unroll 1
        for (int jc = 0; jc < 8; jc++) {       // chunks of 16 keys
            const int kbase = kt * 128 + jc * 16;
            const int yk  = kbase >> 5;
            const int xk0 = kbase & 31;
            // Within a chunk idx decreases by 1 per key: tb[C - j]
            const int C0 = (yq0 - yk + 31) * 63 + (xq0 - xk0 + 31);
            const int C1 = (yq1 - yk + 31) * 63 + (xq1 - xk0 + 31);

            float sc0[16], sc1[16];
            #pragma unroll
            for (int j = 0; j < 16; j++) {
                const ulonglong2* kp = (const ulonglong2*)&Ks[(jc * 16 + j) * 8];
                u64 acc0 = 0ull, acc1 = 0ull;
                #pragma unroll
                for (int u = 0; u < 8; u++) {
                    ulonglong2 kv = kp[u];
                    ffma2(acc0, q0[2*u],   kv.x);
                    ffma2(acc0, q0[2*u+1], kv.y);
                    ffma2(acc1, q1[2*u],   kv.x);
                    ffma2(acc1, q1[2*u+1], kv.y);
                }
                float2 x0 = upk2(acc0), x1 = upk2(acc1);
                sc0[j] = x0.x + x0.y + tb[C0 - j];
                sc1[j] = x1.x + x1.y + tb[C1 - j];
            }

            // online softmax update (both queries)
            float mx0 = sc0[0], mx1 = sc1[0];
            #pragma unroll
            for (int j = 1; j < 16; j++) {
                mx0 = fmaxf(mx0, sc0[j]);
                mx1 = fmaxf(mx1, sc1[j]);
            }
            float nm0 = fmaxf(m0, mx0), nm1 = fmaxf(m1, mx1);
            float c0 = __expf(m0 - nm0), c1 = __expf(m1 - nm1);
            m0 = nm0; m1 = nm1;
            l0 *= c0;  l1 *= c1;
            u64 cc0 = pk2(c0, c0), cc1 = pk2(c1, c1);
            #pragma unroll
            for (int u = 0; u < 16; u++) {
                fmul2(a0[u], a0[u], cc0);
                fmul2(a1[u], a1[u], cc1);
            }
            #pragma unroll
            for (int j = 0; j < 16; j++) {
                float p0 = __expf(sc0[j] - m0);
                float p1 = __expf(sc1[j] - m1);
                l0 += p0; l1 += p1;
                u64 pp0 = pk2(p0, p0), pp1 = pk2(p1, p1);
                const ulonglong2* vp = (const ulonglong2*)&Vs[(jc * 16 + j) * 8];
                #pragma unroll
                for (int u = 0; u < 8; u++) {
                    ulonglong2 vv = vp[u];
                    ffma2(a0[2*u],   pp0, vv.x);
                    ffma2(a0[2*u+1], pp0, vv.y);
                    ffma2(a1[2*u],   pp1, vv.x);
                    ffma2(a1[2*u+1], pp1, vv.y);
                }
            }
        }
    }

    const float inv0 = 1.f / l0;
    const float inv1 = 1.f / l1;
    float4* xo0 = (float4*)(X + ((size_t)(b * SEQ + s0)) * CTOT + h * HD);
    float4* xo1 = (float4*)(X + ((size_t)(b * SEQ + s1)) * CTOT + h * HD);
    #pragma unroll
    for (int u = 0; u < 8; u++) {
        float2 p0 = upk2(a0[2*u]), p1 = upk2(a0[2*u+1]);
        float4 v;
        v.x = p0.x * inv0; v.y = p0.y * inv0;
        v.z = p1.x * inv0; v.w = p1.y * inv0;
        xo0[u] = v;
        float2 r0 = upk2(a1[2*u]), r1 = upk2(a1[2*u+1]);
        float4 w;
        w.x = r0.x * inv1; w.y = r0.y * inv1;
        w.z = r1.x * inv1; w.w = r1.y * inv1;
        xo1[u] = w;
    }
}

// ---------------------------------------------------------------------------
extern "C" void kernel_launch(void* const* d_in, const int* in_sizes, int n_in,
                              void* d_out, int out_size)
{
    const float* xq  = (const float*)d_in[0];
    const float* xkv = (const float*)d_in[1];
    const float* Wq  = (const float*)d_in[2];
    const float* bq  = (const float*)d_in[3];
    const float* Wk  = (const float*)d_in[4];
    const float* bk  = (const float*)d_in[5];
    const float* Wv  = (const float*)d_in[6];
    const float* bv  = (const float*)d_in[7];
    const float* rel = (const float*)d_in[8];
    const float* Wo  = (const float*)d_in[9];
    const float* bo  = (const float*)d_in[10];

    void *pq, *pk, *pv, *px;
    cudaGetSymbolAddress(&pq, g_Q);
    cudaGetSymbolAddress(&pk, g_K);
    cudaGetSymbolAddress(&pv, g_V);
    cudaGetSymbolAddress(&px, g_X);

    // Max shared carveout hint (idempotent, no alloc; capture-safe).
    cudaFuncSetAttribute(attn_kernel,
                         cudaFuncAttributePreferredSharedMemoryCarveout, 100);

    const float qscale = 0.17677669529663687f;  // 1/sqrt(32)

    dim3 gg(MTOT / 64, CTOT / 128);             // (128, 2) = 256 CTAs
    gemm_kernel<<<gg, 128>>>(xq,  Wq, bq, (float*)pq, qscale, 1);
    gemm_kernel<<<gg, 128>>>(xkv, Wk, bk, (float*)pk, 1.f,    1);
    gemm_kernel<<<gg, 128>>>(xkv, Wv, bv, (float*)pv, 1.f,    1);

    attn_kernel<<<dim3(4, 64), 128>>>((const float*)pq, (const float*)pk,
                                      (const float*)pv, rel, (float*)px);

    gemm_kernel<<<gg, 128>>>((const float*)px, Wo, bo, (float*)d_out, 1.f, 0);
}